// round 2
// baseline (speedup 1.0000x reference)
#include <cuda_runtime.h>
#include <math.h>

#define BATCH 2
#define SEQ   2048
#define CDIM  1024
#define HEADS 16
#define HD    64
#define SCALE 0.125f
#define LOG2E 1.44269504088896f

#define BHN   (BATCH*HEADS)
#define ROWS  (BATCH*SEQ)
#define QKVN  (3*CDIM)

__device__ float g_Q[BATCH*HEADS*SEQ*HD];
__device__ float g_K[BATCH*HEADS*SEQ*HD];
__device__ float g_V[BATCH*HEADS*SEQ*HD];
__device__ float g_att_fallback[BATCH*SEQ*CDIM];

// ---------------------------------------------------------------------------
// Kernel 1: QKV GEMM, 128x128 tile, BK=8, double-buffered smem, 8x8/thread.
// ---------------------------------------------------------------------------
__global__ __launch_bounds__(256, 2) void qkv_gemm(const float* __restrict__ X,
                                                   const float* __restrict__ W) {
    __shared__ float As[2][8][128];
    __shared__ float Bs[2][8][128];

    const int tid = threadIdx.x;
    const int m0 = blockIdx.y * 128;
    const int n0 = blockIdx.x * 128;

    float acc[8][8];
#pragma unroll
    for (int i = 0; i < 8; i++)
#pragma unroll
        for (int j = 0; j < 8; j++) acc[i][j] = 0.f;

    const int tr = (tid >> 4) * 8;
    const int tc = (tid & 15) * 8;

    // A load: 128x8 = 256 float4. row = tid>>1, kc = (tid&1)*4
    const int arow = tid >> 1, akc = (tid & 1) * 4;
    // B load: 8x128 = 256 float4. krow = tid>>5, col = (tid&31)*4
    const int bkrow = tid >> 5, bcol = (tid & 31) * 4;

    const float* aptr = X + (size_t)(m0 + arow) * CDIM + akc;
    const float* bptr = W + (size_t)bkrow * QKVN + n0 + bcol;

    float4 pa = *(const float4*)aptr;
    float4 pb = *(const float4*)bptr;

    int buf = 0;
    As[0][akc + 0][arow] = pa.x;
    As[0][akc + 1][arow] = pa.y;
    As[0][akc + 2][arow] = pa.z;
    As[0][akc + 3][arow] = pa.w;
    *(float4*)&Bs[0][bkrow][bcol] = pb;
    __syncthreads();

    for (int k0 = 8; k0 < CDIM; k0 += 8) {
        pa = *(const float4*)(aptr + k0);
        pb = *(const float4*)(bptr + (size_t)k0 * QKVN);

#pragma unroll
        for (int kk = 0; kk < 8; kk++) {
            float ar[8], br[8];
            *(float4*)&ar[0] = *(float4*)&As[buf][kk][tr];
            *(float4*)&ar[4] = *(float4*)&As[buf][kk][tr + 4];
            *(float4*)&br[0] = *(float4*)&Bs[buf][kk][tc];
            *(float4*)&br[4] = *(float4*)&Bs[buf][kk][tc + 4];
#pragma unroll
            for (int i = 0; i < 8; i++)
#pragma unroll
                for (int j = 0; j < 8; j++) acc[i][j] += ar[i] * br[j];
        }

        As[buf ^ 1][akc + 0][arow] = pa.x;
        As[buf ^ 1][akc + 1][arow] = pa.y;
        As[buf ^ 1][akc + 2][arow] = pa.z;
        As[buf ^ 1][akc + 3][arow] = pa.w;
        *(float4*)&Bs[buf ^ 1][bkrow][bcol] = pb;
        __syncthreads();
        buf ^= 1;
    }
#pragma unroll
    for (int kk = 0; kk < 8; kk++) {
        float ar[8], br[8];
        *(float4*)&ar[0] = *(float4*)&As[buf][kk][tr];
        *(float4*)&ar[4] = *(float4*)&As[buf][kk][tr + 4];
        *(float4*)&br[0] = *(float4*)&Bs[buf][kk][tc];
        *(float4*)&br[4] = *(float4*)&Bs[buf][kk][tc + 4];
#pragma unroll
        for (int i = 0; i < 8; i++)
#pragma unroll
            for (int j = 0; j < 8; j++) acc[i][j] += ar[i] * br[j];
    }

    // Scatter epilogue into (B,H,N,D) Q/K/V
    const int c = n0 + tc;
    const int s = c >> 10;
    const int h = (c & 1023) >> 6;
    const int dd = c & 63;
    float* dst = (s == 0) ? g_Q : (s == 1) ? g_K : g_V;
#pragma unroll
    for (int i = 0; i < 8; i++) {
        int m = m0 + tr + i;
        int b = m >> 11;
        int n = m & 2047;
        float* p = dst + ((((size_t)b * HEADS + h) * SEQ + n) * HD + dd);
        *(float4*)p = make_float4(acc[i][0], acc[i][1], acc[i][2], acc[i][3]);
        *(float4*)(p + 4) = make_float4(acc[i][4], acc[i][5], acc[i][6], acc[i][7]);
    }
}

// ---------------------------------------------------------------------------
// Kernel 2: flash attention, 1 query row/thread, 4-way split QK accumulators,
// exp2-domain softmax (SCALE*log2e folded into q).
// ---------------------------------------------------------------------------
__global__ __launch_bounds__(128) void flash_attn(float* __restrict__ out2) {
    __shared__ float ks[64 * HD];
    __shared__ float vs[64 * HD];

    const int tid = threadIdx.x;
    const int bh = blockIdx.y;
    const int row = blockIdx.x * 128 + tid;

    const float QF = SCALE * LOG2E;
    const float* qp = g_Q + ((size_t)bh * SEQ + row) * HD;
    float q[HD];
#pragma unroll
    for (int d4 = 0; d4 < 16; d4++) {
        float4 t = *(const float4*)&qp[d4 * 4];
        q[d4 * 4 + 0] = t.x * QF;
        q[d4 * 4 + 1] = t.y * QF;
        q[d4 * 4 + 2] = t.z * QF;
        q[d4 * 4 + 3] = t.w * QF;
    }

    float acc[HD];
#pragma unroll
    for (int d = 0; d < HD; d++) acc[d] = 0.f;
    float mx = -1e30f, l = 0.f;

    const float4* kbase = (const float4*)(g_K + (size_t)bh * SEQ * HD);
    const float4* vbase = (const float4*)(g_V + (size_t)bh * SEQ * HD);

    for (int kt = 0; kt < SEQ / 64; kt++) {
        const float4* ksrc = kbase + kt * (64 * HD / 4);
        const float4* vsrc = vbase + kt * (64 * HD / 4);
#pragma unroll
        for (int i = 0; i < 8; i++) {
            ((float4*)ks)[tid + i * 128] = ksrc[tid + i * 128];
            ((float4*)vs)[tid + i * 128] = vsrc[tid + i * 128];
        }
        __syncthreads();

#pragma unroll
        for (int jc = 0; jc < 4; jc++) {
            float sv[16];
#pragma unroll
            for (int j = 0; j < 16; j++) {
                const float4* kr = (const float4*)(ks + (jc * 16 + j) * HD);
                float s0 = 0.f, s1 = 0.f, s2 = 0.f, s3 = 0.f;
#pragma unroll
                for (int d4 = 0; d4 < 16; d4++) {
                    float4 kk = kr[d4];
                    s0 += q[d4 * 4 + 0] * kk.x;
                    s1 += q[d4 * 4 + 1] * kk.y;
                    s2 += q[d4 * 4 + 2] * kk.z;
                    s3 += q[d4 * 4 + 3] * kk.w;
                }
                sv[j] = (s0 + s1) + (s2 + s3);
            }
            float cm = mx;
#pragma unroll
            for (int j = 0; j < 16; j++) cm = fmaxf(cm, sv[j]);
            float corr = exp2f(mx - cm);
            mx = cm;
            l *= corr;
#pragma unroll
            for (int j = 0; j < 16; j++) {
                sv[j] = exp2f(sv[j] - cm);
                l += sv[j];
            }
#pragma unroll
            for (int d = 0; d < HD; d++) acc[d] *= corr;
#pragma unroll
            for (int j = 0; j < 16; j++) {
                const float4* vr = (const float4*)(vs + (jc * 16 + j) * HD);
                float pj = sv[j];
#pragma unroll
                for (int d4 = 0; d4 < 16; d4++) {
                    float4 vv = vr[d4];
                    acc[d4 * 4 + 0] += pj * vv.x;
                    acc[d4 * 4 + 1] += pj * vv.y;
                    acc[d4 * 4 + 2] += pj * vv.z;
                    acc[d4 * 4 + 3] += pj * vv.w;
                }
            }
        }
        __syncthreads();
    }

    const float inv = 1.f / l;
    const int b = bh >> 4;
    const int h = bh & 15;
    float* op = out2 + (((size_t)b * SEQ + row) * CDIM + h * HD);
#pragma unroll
    for (int d4 = 0; d4 < 16; d4++) {
        ((float4*)op)[d4] = make_float4(acc[d4 * 4 + 0] * inv, acc[d4 * 4 + 1] * inv,
                                        acc[d4 * 4 + 2] * inv, acc[d4 * 4 + 3] * inv);
    }
}

// ---------------------------------------------------------------------------
// Kernel 3: proj GEMM, same double-buffered structure. out = (att2+f)@W + b
// ---------------------------------------------------------------------------
__global__ __launch_bounds__(256, 2) void proj_gemm(const float* __restrict__ att2,
                                                    const float* __restrict__ F,
                                                    const float* __restrict__ W,
                                                    const float* __restrict__ bias,
                                                    float* __restrict__ out) {
    __shared__ float As[2][8][128];
    __shared__ float Bs[2][8][128];

    const int tid = threadIdx.x;
    const int m0 = blockIdx.y * 128;
    const int n0 = blockIdx.x * 128;

    float acc[8][8];
#pragma unroll
    for (int i = 0; i < 8; i++)
#pragma unroll
        for (int j = 0; j < 8; j++) acc[i][j] = 0.f;

    const int tr = (tid >> 4) * 8;
    const int tc = (tid & 15) * 8;

    const int arow = tid >> 1, akc = (tid & 1) * 4;
    const int bkrow = tid >> 5, bcol = (tid & 31) * 4;

    const float* aptr = att2 + (size_t)(m0 + arow) * CDIM + akc;
    const float* fptr = F + (size_t)(m0 + arow) * CDIM + akc;
    const float* bptr = W + (size_t)bkrow * CDIM + n0 + bcol;

    float4 pa = *(const float4*)aptr;
    float4 pf = *(const float4*)fptr;
    float4 pb = *(const float4*)bptr;

    int buf = 0;
    As[0][akc + 0][arow] = pa.x + pf.x;
    As[0][akc + 1][arow] = pa.y + pf.y;
    As[0][akc + 2][arow] = pa.z + pf.z;
    As[0][akc + 3][arow] = pa.w + pf.w;
    *(float4*)&Bs[0][bkrow][bcol] = pb;
    __syncthreads();

    for (int k0 = 8; k0 < CDIM; k0 += 8) {
        pa = *(const float4*)(aptr + k0);
        pf = *(const float4*)(fptr + k0);
        pb = *(const float4*)(bptr + (size_t)k0 * CDIM);

#pragma unroll
        for (int kk = 0; kk < 8; kk++) {
            float ar[8], br[8];
            *(float4*)&ar[0] = *(float4*)&As[buf][kk][tr];
            *(float4*)&ar[4] = *(float4*)&As[buf][kk][tr + 4];
            *(float4*)&br[0] = *(float4*)&Bs[buf][kk][tc];
            *(float4*)&br[4] = *(float4*)&Bs[buf][kk][tc + 4];
#pragma unroll
            for (int i = 0; i < 8; i++)
#pragma unroll
                for (int j = 0; j < 8; j++) acc[i][j] += ar[i] * br[j];
        }

        As[buf ^ 1][akc + 0][arow] = pa.x + pf.x;
        As[buf ^ 1][akc + 1][arow] = pa.y + pf.y;
        As[buf ^ 1][akc + 2][arow] = pa.z + pf.z;
        As[buf ^ 1][akc + 3][arow] = pa.w + pf.w;
        *(float4*)&Bs[buf ^ 1][bkrow][bcol] = pb;
        __syncthreads();
        buf ^= 1;
    }
#pragma unroll
    for (int kk = 0; kk < 8; kk++) {
        float ar[8], br[8];
        *(float4*)&ar[0] = *(float4*)&As[buf][kk][tr];
        *(float4*)&ar[4] = *(float4*)&As[buf][kk][tr + 4];
        *(float4*)&br[0] = *(float4*)&Bs[buf][kk][tc];
        *(float4*)&br[4] = *(float4*)&Bs[buf][kk][tc + 4];
#pragma unroll
        for (int i = 0; i < 8; i++)
#pragma unroll
            for (int j = 0; j < 8; j++) acc[i][j] += ar[i] * br[j];
    }

    float bb[8];
    *(float4*)&bb[0] = *(const float4*)&bias[n0 + tc];
    *(float4*)&bb[4] = *(const float4*)&bias[n0 + tc + 4];
#pragma unroll
    for (int i = 0; i < 8; i++) {
        int m = m0 + tr + i;
        float* p = out + (size_t)m * CDIM + n0 + tc;
        *(float4*)p = make_float4(acc[i][0] + bb[0], acc[i][1] + bb[1],
                                  acc[i][2] + bb[2], acc[i][3] + bb[3]);
        *(float4*)(p + 4) = make_float4(acc[i][4] + bb[4], acc[i][5] + bb[5],
                                        acc[i][6] + bb[6], acc[i][7] + bb[7]);
    }
}

extern "C" void kernel_launch(void* const* d_in, const int* in_sizes, int n_in,
                              void* d_out, int out_size) {
    const float* x     = (const float*)d_in[0];
    const float* f     = (const float*)d_in[1];
    const float* Wqkv  = (const float*)d_in[2];
    const float* Wproj = (const float*)d_in[3];
    const float* bproj = (const float*)d_in[4];
    float* out = (float*)d_out;

    const size_t half = (size_t)BATCH * SEQ * CDIM;
    float* att2;
    if ((size_t)out_size >= 2 * half) {
        att2 = out + half;
    } else {
        cudaGetSymbolAddress((void**)&att2, g_att_fallback);
    }

    qkv_gemm<<<dim3(QKVN / 128, ROWS / 128), 256>>>(x, Wqkv);
    flash_attn<<<dim3(SEQ / 128, BHN), 128>>>(att2);
    proj_gemm<<<dim3(CDIM / 128, ROWS / 128), 256>>>(att2, f, Wproj, bproj, out);
}

// round 3
// speedup vs baseline: 2.6562x; 2.6562x over previous
#include <cuda_runtime.h>
#include <math.h>

#define BATCH 2
#define SEQ   2048
#define CDIM  1024
#define HEADS 16
#define HD    64
#define SCALE 0.125f
#define LOG2E 1.44269504088896f

#define BHN   (BATCH*HEADS)
#define ROWS  (BATCH*SEQ)
#define QKVN  (3*CDIM)

__device__ float g_Q[BATCH*HEADS*SEQ*HD];
__device__ float g_K[BATCH*HEADS*SEQ*HD];
__device__ float g_V[BATCH*HEADS*SEQ*HD];
__device__ float g_att_fallback[BATCH*SEQ*CDIM];

// ---------------------------------------------------------------------------
// tf32 helpers
// ---------------------------------------------------------------------------
__device__ __forceinline__ unsigned f2tf32(float x) {
    unsigned u;
    asm("cvt.rna.tf32.f32 %0, %1;" : "=r"(u) : "f"(x));
    return u;
}

__device__ __forceinline__ void mma_tf32(float& d0, float& d1, float& d2, float& d3,
                                         unsigned a0, unsigned a1, unsigned a2, unsigned a3,
                                         unsigned b0, unsigned b1) {
    asm volatile(
        "mma.sync.aligned.m16n8k8.row.col.f32.tf32.tf32.f32 "
        "{%0,%1,%2,%3}, {%4,%5,%6,%7}, {%8,%9}, {%0,%1,%2,%3};"
        : "+f"(d0), "+f"(d1), "+f"(d2), "+f"(d3)
        : "r"(a0), "r"(a1), "r"(a2), "r"(a3), "r"(b0), "r"(b1));
}

// ---------------------------------------------------------------------------
// Kernel 1: QKV GEMM (fp32 FFMA, unchanged)
// ---------------------------------------------------------------------------
__global__ __launch_bounds__(256, 2) void qkv_gemm(const float* __restrict__ X,
                                                   const float* __restrict__ W) {
    __shared__ float As[2][8][128];
    __shared__ float Bs[2][8][128];

    const int tid = threadIdx.x;
    const int m0 = blockIdx.y * 128;
    const int n0 = blockIdx.x * 128;

    float acc[8][8];
#pragma unroll
    for (int i = 0; i < 8; i++)
#pragma unroll
        for (int j = 0; j < 8; j++) acc[i][j] = 0.f;

    const int tr = (tid >> 4) * 8;
    const int tc = (tid & 15) * 8;
    const int arow = tid >> 1, akc = (tid & 1) * 4;
    const int bkrow = tid >> 5, bcol = (tid & 31) * 4;

    const float* aptr = X + (size_t)(m0 + arow) * CDIM + akc;
    const float* bptr = W + (size_t)bkrow * QKVN + n0 + bcol;

    float4 pa = *(const float4*)aptr;
    float4 pb = *(const float4*)bptr;

    int buf = 0;
    As[0][akc + 0][arow] = pa.x;
    As[0][akc + 1][arow] = pa.y;
    As[0][akc + 2][arow] = pa.z;
    As[0][akc + 3][arow] = pa.w;
    *(float4*)&Bs[0][bkrow][bcol] = pb;
    __syncthreads();

    for (int k0 = 8; k0 < CDIM; k0 += 8) {
        pa = *(const float4*)(aptr + k0);
        pb = *(const float4*)(bptr + (size_t)k0 * QKVN);
#pragma unroll
        for (int kk = 0; kk < 8; kk++) {
            float ar[8], br[8];
            *(float4*)&ar[0] = *(float4*)&As[buf][kk][tr];
            *(float4*)&ar[4] = *(float4*)&As[buf][kk][tr + 4];
            *(float4*)&br[0] = *(float4*)&Bs[buf][kk][tc];
            *(float4*)&br[4] = *(float4*)&Bs[buf][kk][tc + 4];
#pragma unroll
            for (int i = 0; i < 8; i++)
#pragma unroll
                for (int j = 0; j < 8; j++) acc[i][j] += ar[i] * br[j];
        }
        As[buf ^ 1][akc + 0][arow] = pa.x;
        As[buf ^ 1][akc + 1][arow] = pa.y;
        As[buf ^ 1][akc + 2][arow] = pa.z;
        As[buf ^ 1][akc + 3][arow] = pa.w;
        *(float4*)&Bs[buf ^ 1][bkrow][bcol] = pb;
        __syncthreads();
        buf ^= 1;
    }
#pragma unroll
    for (int kk = 0; kk < 8; kk++) {
        float ar[8], br[8];
        *(float4*)&ar[0] = *(float4*)&As[buf][kk][tr];
        *(float4*)&ar[4] = *(float4*)&As[buf][kk][tr + 4];
        *(float4*)&br[0] = *(float4*)&Bs[buf][kk][tc];
        *(float4*)&br[4] = *(float4*)&Bs[buf][kk][tc + 4];
#pragma unroll
        for (int i = 0; i < 8; i++)
#pragma unroll
            for (int j = 0; j < 8; j++) acc[i][j] += ar[i] * br[j];
    }

    const int c = n0 + tc;
    const int s = c >> 10;
    const int h = (c & 1023) >> 6;
    const int dd = c & 63;
    float* dst = (s == 0) ? g_Q : (s == 1) ? g_K : g_V;
#pragma unroll
    for (int i = 0; i < 8; i++) {
        int m = m0 + tr + i;
        int b = m >> 11;
        int n = m & 2047;
        float* p = dst + ((((size_t)b * HEADS + h) * SEQ + n) * HD + dd);
        *(float4*)p = make_float4(acc[i][0], acc[i][1], acc[i][2], acc[i][3]);
        *(float4*)(p + 4) = make_float4(acc[i][4], acc[i][5], acc[i][6], acc[i][7]);
    }
}

// ---------------------------------------------------------------------------
// Kernel 2: tensor-core flash attention (tf32 mma.sync.m16n8k8)
// Block: 128 threads = 4 warps, 64 query rows (16 per warp), KV tiles of 64.
// smem strides chosen for conflict-free fragment loads:
//   K stride 68 (bank 4g+t), V stride 72 (bank 8t+g), P stride 68.
// ---------------------------------------------------------------------------
#define SKS 68
#define SVS 72
#define FLASH_SMEM ((64*SKS + 64*SVS + 64*SKS) * 4)

__global__ __launch_bounds__(128) void flash_attn_tc(float* __restrict__ out2) {
    extern __shared__ unsigned smem[];
    unsigned* sK = smem;                       // [64][SKS] tf32
    unsigned* sV = smem + 64 * SKS;            // [64][SVS] tf32
    unsigned* sP = smem + 64 * SKS + 64 * SVS; // [64][SKS] tf32

    const int tid = threadIdx.x;
    const int lane = tid & 31;
    const int w = tid >> 5;
    const int g = lane >> 2;   // group id (row within fragment)
    const int t = lane & 3;    // thread-in-group

    const int bh = blockIdx.y;
    const int q0 = blockIdx.x * 64;
    const float QF = SCALE * LOG2E;

    // --- Q fragments (A layout), scale folded, tf32 ---
    unsigned qa[8][4];
    {
        const float* p0 = g_Q + ((size_t)bh * SEQ + (q0 + w * 16 + g)) * HD;
        const float* p1 = p0 + 8 * HD;
#pragma unroll
        for (int kt = 0; kt < 8; kt++) {
            qa[kt][0] = f2tf32(p0[8 * kt + t] * QF);
            qa[kt][1] = f2tf32(p1[8 * kt + t] * QF);
            qa[kt][2] = f2tf32(p0[8 * kt + t + 4] * QF);
            qa[kt][3] = f2tf32(p1[8 * kt + t + 4] * QF);
        }
    }

    float o[8][4];
#pragma unroll
    for (int nt = 0; nt < 8; nt++)
#pragma unroll
        for (int i = 0; i < 4; i++) o[nt][i] = 0.f;
    float m0 = -1e30f, m1 = -1e30f, l0 = 0.f, l1 = 0.f;

    const float4* Ksrc = (const float4*)(g_K + (size_t)bh * SEQ * HD);
    const float4* Vsrc = (const float4*)(g_V + (size_t)bh * SEQ * HD);

    for (int kv = 0; kv < SEQ / 64; kv++) {
        __syncthreads();
        // fill K/V tiles (convert to tf32 once here; read 4x by the warps)
#pragma unroll
        for (int i = 0; i < 8; i++) {
            int idx = tid + i * 128;          // 0..1023 float4s
            int r = idx >> 4, c4 = (idx & 15) * 4;
            float4 kk = Ksrc[kv * 1024 + idx];
            unsigned* dk = sK + r * SKS + c4;
            dk[0] = f2tf32(kk.x); dk[1] = f2tf32(kk.y);
            dk[2] = f2tf32(kk.z); dk[3] = f2tf32(kk.w);
            float4 vv = Vsrc[kv * 1024 + idx];
            unsigned* dv = sV + r * SVS + c4;
            dv[0] = f2tf32(vv.x); dv[1] = f2tf32(vv.y);
            dv[2] = f2tf32(vv.z); dv[3] = f2tf32(vv.w);
        }
        __syncthreads();

        // --- S = Q @ K^T : 16 rows x 64 keys per warp ---
        float s[8][4];
#pragma unroll
        for (int nt = 0; nt < 8; nt++)
#pragma unroll
            for (int i = 0; i < 4; i++) s[nt][i] = 0.f;

#pragma unroll
        for (int kt = 0; kt < 8; kt++) {
#pragma unroll
            for (int nt = 0; nt < 8; nt++) {
                unsigned b0 = sK[(8 * nt + g) * SKS + 8 * kt + t];
                unsigned b1 = sK[(8 * nt + g) * SKS + 8 * kt + t + 4];
                mma_tf32(s[nt][0], s[nt][1], s[nt][2], s[nt][3],
                         qa[kt][0], qa[kt][1], qa[kt][2], qa[kt][3], b0, b1);
            }
        }

        // --- online softmax (base-2 domain) ---
        float rx0 = -1e30f, rx1 = -1e30f;
#pragma unroll
        for (int nt = 0; nt < 8; nt++) {
            rx0 = fmaxf(rx0, fmaxf(s[nt][0], s[nt][1]));
            rx1 = fmaxf(rx1, fmaxf(s[nt][2], s[nt][3]));
        }
        rx0 = fmaxf(rx0, __shfl_xor_sync(0xffffffffu, rx0, 1));
        rx0 = fmaxf(rx0, __shfl_xor_sync(0xffffffffu, rx0, 2));
        rx1 = fmaxf(rx1, __shfl_xor_sync(0xffffffffu, rx1, 1));
        rx1 = fmaxf(rx1, __shfl_xor_sync(0xffffffffu, rx1, 2));

        float nm0 = fmaxf(m0, rx0), nm1 = fmaxf(m1, rx1);
        float c0 = exp2f(m0 - nm0), c1 = exp2f(m1 - nm1);
        m0 = nm0; m1 = nm1;

        float ps0 = 0.f, ps1 = 0.f;
#pragma unroll
        for (int nt = 0; nt < 8; nt++) {
            s[nt][0] = exp2f(s[nt][0] - nm0);
            s[nt][1] = exp2f(s[nt][1] - nm0);
            s[nt][2] = exp2f(s[nt][2] - nm1);
            s[nt][3] = exp2f(s[nt][3] - nm1);
            ps0 += s[nt][0] + s[nt][1];
            ps1 += s[nt][2] + s[nt][3];
        }
        ps0 += __shfl_xor_sync(0xffffffffu, ps0, 1);
        ps0 += __shfl_xor_sync(0xffffffffu, ps0, 2);
        ps1 += __shfl_xor_sync(0xffffffffu, ps1, 1);
        ps1 += __shfl_xor_sync(0xffffffffu, ps1, 2);
        l0 = l0 * c0 + ps0;
        l1 = l1 * c1 + ps1;

#pragma unroll
        for (int nt = 0; nt < 8; nt++) {
            o[nt][0] *= c0; o[nt][1] *= c0;
            o[nt][2] *= c1; o[nt][3] *= c1;
        }

        // --- store P (tf32) to warp-private smem slice ---
        unsigned* pr0 = sP + (w * 16 + g) * SKS;
        unsigned* pr1 = pr0 + 8 * SKS;
#pragma unroll
        for (int nt = 0; nt < 8; nt++) {
            *(uint2*)(pr0 + 8 * nt + 2 * t) = make_uint2(f2tf32(s[nt][0]), f2tf32(s[nt][1]));
            *(uint2*)(pr1 + 8 * nt + 2 * t) = make_uint2(f2tf32(s[nt][2]), f2tf32(s[nt][3]));
        }
        __syncwarp();

        // --- O += P @ V ---
#pragma unroll
        for (int kt = 0; kt < 8; kt++) {
            unsigned pa0 = pr0[8 * kt + t];
            unsigned pa1 = pr1[8 * kt + t];
            unsigned pa2 = pr0[8 * kt + t + 4];
            unsigned pa3 = pr1[8 * kt + t + 4];
#pragma unroll
            for (int nt = 0; nt < 8; nt++) {
                unsigned b0 = sV[(8 * kt + t) * SVS + 8 * nt + g];
                unsigned b1 = sV[(8 * kt + t + 4) * SVS + 8 * nt + g];
                mma_tf32(o[nt][0], o[nt][1], o[nt][2], o[nt][3],
                         pa0, pa1, pa2, pa3, b0, b1);
            }
        }
    }

    // --- epilogue ---
    const float inv0 = 1.f / l0, inv1 = 1.f / l1;
    const int b = bh >> 4, h = bh & 15;
    const int r0 = q0 + w * 16 + g;
    float* op0 = out2 + ((size_t)b * SEQ + r0) * CDIM + h * HD;
    float* op1 = op0 + (size_t)8 * CDIM;
#pragma unroll
    for (int nt = 0; nt < 8; nt++) {
        *(float2*)(op0 + 8 * nt + 2 * t) = make_float2(o[nt][0] * inv0, o[nt][1] * inv0);
        *(float2*)(op1 + 8 * nt + 2 * t) = make_float2(o[nt][2] * inv1, o[nt][3] * inv1);
    }
}

// ---------------------------------------------------------------------------
// Kernel 3: proj GEMM (fp32 FFMA, unchanged). out = (att2+f)@W + b
// ---------------------------------------------------------------------------
__global__ __launch_bounds__(256, 2) void proj_gemm(const float* __restrict__ att2,
                                                    const float* __restrict__ F,
                                                    const float* __restrict__ W,
                                                    const float* __restrict__ bias,
                                                    float* __restrict__ out) {
    __shared__ float As[2][8][128];
    __shared__ float Bs[2][8][128];

    const int tid = threadIdx.x;
    const int m0 = blockIdx.y * 128;
    const int n0 = blockIdx.x * 128;

    float acc[8][8];
#pragma unroll
    for (int i = 0; i < 8; i++)
#pragma unroll
        for (int j = 0; j < 8; j++) acc[i][j] = 0.f;

    const int tr = (tid >> 4) * 8;
    const int tc = (tid & 15) * 8;
    const int arow = tid >> 1, akc = (tid & 1) * 4;
    const int bkrow = tid >> 5, bcol = (tid & 31) * 4;

    const float* aptr = att2 + (size_t)(m0 + arow) * CDIM + akc;
    const float* fptr = F + (size_t)(m0 + arow) * CDIM + akc;
    const float* bptr = W + (size_t)bkrow * CDIM + n0 + bcol;

    float4 pa = *(const float4*)aptr;
    float4 pf = *(const float4*)fptr;
    float4 pb = *(const float4*)bptr;

    int buf = 0;
    As[0][akc + 0][arow] = pa.x + pf.x;
    As[0][akc + 1][arow] = pa.y + pf.y;
    As[0][akc + 2][arow] = pa.z + pf.z;
    As[0][akc + 3][arow] = pa.w + pf.w;
    *(float4*)&Bs[0][bkrow][bcol] = pb;
    __syncthreads();

    for (int k0 = 8; k0 < CDIM; k0 += 8) {
        pa = *(const float4*)(aptr + k0);
        pf = *(const float4*)(fptr + k0);
        pb = *(const float4*)(bptr + (size_t)k0 * CDIM);
#pragma unroll
        for (int kk = 0; kk < 8; kk++) {
            float ar[8], br[8];
            *(float4*)&ar[0] = *(float4*)&As[buf][kk][tr];
            *(float4*)&ar[4] = *(float4*)&As[buf][kk][tr + 4];
            *(float4*)&br[0] = *(float4*)&Bs[buf][kk][tc];
            *(float4*)&br[4] = *(float4*)&Bs[buf][kk][tc + 4];
#pragma unroll
            for (int i = 0; i < 8; i++)
#pragma unroll
                for (int j = 0; j < 8; j++) acc[i][j] += ar[i] * br[j];
        }
        As[buf ^ 1][akc + 0][arow] = pa.x + pf.x;
        As[buf ^ 1][akc + 1][arow] = pa.y + pf.y;
        As[buf ^ 1][akc + 2][arow] = pa.z + pf.z;
        As[buf ^ 1][akc + 3][arow] = pa.w + pf.w;
        *(float4*)&Bs[buf ^ 1][bkrow][bcol] = pb;
        __syncthreads();
        buf ^= 1;
    }
#pragma unroll
    for (int kk = 0; kk < 8; kk++) {
        float ar[8], br[8];
        *(float4*)&ar[0] = *(float4*)&As[buf][kk][tr];
        *(float4*)&ar[4] = *(float4*)&As[buf][kk][tr + 4];
        *(float4*)&br[0] = *(float4*)&Bs[buf][kk][tc];
        *(float4*)&br[4] = *(float4*)&Bs[buf][kk][tc + 4];
#pragma unroll
        for (int i = 0; i < 8; i++)
#pragma unroll
            for (int j = 0; j < 8; j++) acc[i][j] += ar[i] * br[j];
    }

    float bb[8];
    *(float4*)&bb[0] = *(const float4*)&bias[n0 + tc];
    *(float4*)&bb[4] = *(const float4*)&bias[n0 + tc + 4];
#pragma unroll
    for (int i = 0; i < 8; i++) {
        int m = m0 + tr + i;
        float* p = out + (size_t)m * CDIM + n0 + tc;
        *(float4*)p = make_float4(acc[i][0] + bb[0], acc[i][1] + bb[1],
                                  acc[i][2] + bb[2], acc[i][3] + bb[3]);
        *(float4*)(p + 4) = make_float4(acc[i][4] + bb[4], acc[i][5] + bb[5],
                                        acc[i][6] + bb[6], acc[i][7] + bb[7]);
    }
}

extern "C" void kernel_launch(void* const* d_in, const int* in_sizes, int n_in,
                              void* d_out, int out_size) {
    const float* x     = (const float*)d_in[0];
    const float* f     = (const float*)d_in[1];
    const float* Wqkv  = (const float*)d_in[2];
    const float* Wproj = (const float*)d_in[3];
    const float* bproj = (const float*)d_in[4];
    float* out = (float*)d_out;

    const size_t half = (size_t)BATCH * SEQ * CDIM;
    float* att2;
    if ((size_t)out_size >= 2 * half) {
        att2 = out + half;
    } else {
        cudaGetSymbolAddress((void**)&att2, g_att_fallback);
    }

    cudaFuncSetAttribute(flash_attn_tc, cudaFuncAttributeMaxDynamicSharedMemorySize,
                         FLASH_SMEM);

    qkv_gemm<<<dim3(QKVN / 128, ROWS / 128), 256>>>(x, Wqkv);
    flash_attn_tc<<<dim3(SEQ / 64, BHN), 128, FLASH_SMEM>>>(att2);
    proj_gemm<<<dim3(CDIM / 128, ROWS / 128), 256>>>(att2, f, Wproj, bproj, out);
}

// round 4
// speedup vs baseline: 5.2909x; 1.9919x over previous
#include <cuda_runtime.h>
#include <math.h>

#define BATCH 2
#define SEQ   2048
#define CDIM  1024
#define HEADS 16
#define HD    64
#define SCALE 0.125f
#define LOG2E 1.44269504088896f

#define BHN   (BATCH*HEADS)
#define ROWS  (BATCH*SEQ)
#define QKVN  (3*CDIM)

__device__ float g_Q[BATCH*HEADS*SEQ*HD];
__device__ float g_K[BATCH*HEADS*SEQ*HD];
__device__ float g_V[BATCH*HEADS*SEQ*HD];
__device__ float g_att_fallback[BATCH*SEQ*CDIM];

// ---------------------------------------------------------------------------
// tf32 helpers
// ---------------------------------------------------------------------------
__device__ __forceinline__ unsigned f2tf32(float x) {
    unsigned u;
    asm("cvt.rna.tf32.f32 %0, %1;" : "=r"(u) : "f"(x));
    return u;
}

__device__ __forceinline__ void mma_tf32(float* d,
                                         unsigned a0, unsigned a1, unsigned a2, unsigned a3,
                                         unsigned b0, unsigned b1) {
    asm volatile(
        "mma.sync.aligned.m16n8k8.row.col.f32.tf32.tf32.f32 "
        "{%0,%1,%2,%3}, {%4,%5,%6,%7}, {%8,%9}, {%0,%1,%2,%3};"
        : "+f"(d[0]), "+f"(d[1]), "+f"(d[2]), "+f"(d[3])
        : "r"(a0), "r"(a1), "r"(a2), "r"(a3), "r"(b0), "r"(b1));
}

// ---------------------------------------------------------------------------
// Shared tensor-core GEMM mainloop pieces (128x128 block, 4 warps 64x64, BK=16)
// smem layout: s[k][col] with row stride SAW=136 words (== 8 mod 32):
// fragment reads (banks 8t+g) are conflict-free.
// ---------------------------------------------------------------------------
#define SAW 136

// ---------------------------------------------------------------------------
// Kernel 1: QKV GEMM (tf32 mma) + scatter into (B,H,N,D) Q/K/V
// ---------------------------------------------------------------------------
__global__ __launch_bounds__(128, 2) void qkv_tc(const float* __restrict__ X,
                                                 const float* __restrict__ W) {
    __shared__ unsigned sA[2][16][SAW];
    __shared__ unsigned sB[2][16][SAW];

    const int tid = threadIdx.x;
    const int lane = tid & 31;
    const int w = tid >> 5;
    const int g = lane >> 2, t = lane & 3;
    const int wm = w & 1, wn = w >> 1;

    const int m0 = blockIdx.y * 128;
    const int n0 = blockIdx.x * 128;

    float acc[4][8][4];
#pragma unroll
    for (int mt = 0; mt < 4; mt++)
#pragma unroll
        for (int nt = 0; nt < 8; nt++)
#pragma unroll
            for (int i = 0; i < 4; i++) acc[mt][nt][i] = 0.f;

    // A load: thread handles m = (tid>>2)+32i, k-group = tid&3
    const int am = tid >> 2, at = tid & 3;
    // B load: thread handles k = (tid>>5)+4i, n = 4*(tid&31)
    const int bk = tid >> 5, bn = 4 * (tid & 31);

    const float* aptr = X + (size_t)(m0 + am) * CDIM + 4 * at;
    const float* bptr = W + (size_t)bk * QKVN + n0 + bn;

    float4 ra[4], rb[4];
#pragma unroll
    for (int i = 0; i < 4; i++) {
        ra[i] = *(const float4*)(aptr + (size_t)(32 * i) * CDIM);
        rb[i] = *(const float4*)(bptr + (size_t)(4 * i) * QKVN);
    }

    int buf = 0;
#pragma unroll
    for (int i = 0; i < 4; i++) {
        unsigned* da = &sA[0][4 * at][am + 32 * i];
        da[0 * SAW] = f2tf32(ra[i].x);
        da[1 * SAW] = f2tf32(ra[i].y);
        da[2 * SAW] = f2tf32(ra[i].z);
        da[3 * SAW] = f2tf32(ra[i].w);
        uint4 pb = make_uint4(f2tf32(rb[i].x), f2tf32(rb[i].y),
                              f2tf32(rb[i].z), f2tf32(rb[i].w));
        *(uint4*)&sB[0][bk + 4 * i][bn] = pb;
    }
    __syncthreads();

    for (int k0 = 16; k0 <= CDIM; k0 += 16) {
        if (k0 < CDIM) {
#pragma unroll
            for (int i = 0; i < 4; i++) {
                ra[i] = *(const float4*)(aptr + (size_t)(32 * i) * CDIM + k0);
                rb[i] = *(const float4*)(bptr + (size_t)(k0 + 4 * i) * QKVN);
            }
        }

#pragma unroll
        for (int kt = 0; kt < 2; kt++) {
            unsigned af[4][4];
#pragma unroll
            for (int mt = 0; mt < 4; mt++) {
                int mr = wm * 64 + mt * 16;
                af[mt][0] = sA[buf][kt * 8 + t][mr + g];
                af[mt][1] = sA[buf][kt * 8 + t][mr + g + 8];
                af[mt][2] = sA[buf][kt * 8 + t + 4][mr + g];
                af[mt][3] = sA[buf][kt * 8 + t + 4][mr + g + 8];
            }
#pragma unroll
            for (int nt = 0; nt < 8; nt++) {
                int nc = wn * 64 + nt * 8 + g;
                unsigned b0 = sB[buf][kt * 8 + t][nc];
                unsigned b1 = sB[buf][kt * 8 + t + 4][nc];
#pragma unroll
                for (int mt = 0; mt < 4; mt++)
                    mma_tf32(acc[mt][nt], af[mt][0], af[mt][1], af[mt][2], af[mt][3], b0, b1);
            }
        }

        if (k0 < CDIM) {
#pragma unroll
            for (int i = 0; i < 4; i++) {
                unsigned* da = &sA[buf ^ 1][4 * at][am + 32 * i];
                da[0 * SAW] = f2tf32(ra[i].x);
                da[1 * SAW] = f2tf32(ra[i].y);
                da[2 * SAW] = f2tf32(ra[i].z);
                da[3 * SAW] = f2tf32(ra[i].w);
                uint4 pb = make_uint4(f2tf32(rb[i].x), f2tf32(rb[i].y),
                                      f2tf32(rb[i].z), f2tf32(rb[i].w));
                *(uint4*)&sB[buf ^ 1][bk + 4 * i][bn] = pb;
            }
            __syncthreads();
            buf ^= 1;
        }
    }

    // scatter epilogue: col -> (s,h,dd), row -> (b,n)
#pragma unroll
    for (int mt = 0; mt < 4; mt++) {
#pragma unroll
        for (int nt = 0; nt < 8; nt++) {
            int col = n0 + wn * 64 + nt * 8 + 2 * t;
            int s = col >> 10;
            int h = (col >> 6) & 15;
            int dd = col & 63;
            float* dst = (s == 0) ? g_Q : (s == 1) ? g_K : g_V;
            int row0 = m0 + wm * 64 + mt * 16 + g;
#pragma unroll
            for (int half = 0; half < 2; half++) {
                int row = row0 + 8 * half;
                int b = row >> 11, n = row & 2047;
                float* p = dst + ((((size_t)b * HEADS + h) * SEQ + n) * HD + dd);
                *(float2*)p = make_float2(acc[mt][nt][2 * half], acc[mt][nt][2 * half + 1]);
            }
        }
    }
}

// ---------------------------------------------------------------------------
// Kernel 2: tensor-core flash attention (unchanged from round 3)
// ---------------------------------------------------------------------------
#define SKS 68
#define SVS 72
#define FLASH_SMEM ((64*SKS + 64*SVS + 64*SKS) * 4)

__global__ __launch_bounds__(128) void flash_attn_tc(float* __restrict__ out2) {
    extern __shared__ unsigned smem[];
    unsigned* sK = smem;
    unsigned* sV = smem + 64 * SKS;
    unsigned* sP = smem + 64 * SKS + 64 * SVS;

    const int tid = threadIdx.x;
    const int lane = tid & 31;
    const int w = tid >> 5;
    const int g = lane >> 2;
    const int t = lane & 3;

    const int bh = blockIdx.y;
    const int q0 = blockIdx.x * 64;
    const float QF = SCALE * LOG2E;

    unsigned qa[8][4];
    {
        const float* p0 = g_Q + ((size_t)bh * SEQ + (q0 + w * 16 + g)) * HD;
        const float* p1 = p0 + 8 * HD;
#pragma unroll
        for (int kt = 0; kt < 8; kt++) {
            qa[kt][0] = f2tf32(p0[8 * kt + t] * QF);
            qa[kt][1] = f2tf32(p1[8 * kt + t] * QF);
            qa[kt][2] = f2tf32(p0[8 * kt + t + 4] * QF);
            qa[kt][3] = f2tf32(p1[8 * kt + t + 4] * QF);
        }
    }

    float o[8][4];
#pragma unroll
    for (int nt = 0; nt < 8; nt++)
#pragma unroll
        for (int i = 0; i < 4; i++) o[nt][i] = 0.f;
    float m0 = -1e30f, m1 = -1e30f, l0 = 0.f, l1 = 0.f;

    const float4* Ksrc = (const float4*)(g_K + (size_t)bh * SEQ * HD);
    const float4* Vsrc = (const float4*)(g_V + (size_t)bh * SEQ * HD);

    for (int kv = 0; kv < SEQ / 64; kv++) {
        __syncthreads();
#pragma unroll
        for (int i = 0; i < 8; i++) {
            int idx = tid + i * 128;
            int r = idx >> 4, c4 = (idx & 15) * 4;
            float4 kk = Ksrc[kv * 1024 + idx];
            unsigned* dk = sK + r * SKS + c4;
            dk[0] = f2tf32(kk.x); dk[1] = f2tf32(kk.y);
            dk[2] = f2tf32(kk.z); dk[3] = f2tf32(kk.w);
            float4 vv = Vsrc[kv * 1024 + idx];
            unsigned* dv = sV + r * SVS + c4;
            dv[0] = f2tf32(vv.x); dv[1] = f2tf32(vv.y);
            dv[2] = f2tf32(vv.z); dv[3] = f2tf32(vv.w);
        }
        __syncthreads();

        float s[8][4];
#pragma unroll
        for (int nt = 0; nt < 8; nt++)
#pragma unroll
            for (int i = 0; i < 4; i++) s[nt][i] = 0.f;

#pragma unroll
        for (int kt = 0; kt < 8; kt++) {
#pragma unroll
            for (int nt = 0; nt < 8; nt++) {
                unsigned b0 = sK[(8 * nt + g) * SKS + 8 * kt + t];
                unsigned b1 = sK[(8 * nt + g) * SKS + 8 * kt + t + 4];
                mma_tf32(s[nt], qa[kt][0], qa[kt][1], qa[kt][2], qa[kt][3], b0, b1);
            }
        }

        float rx0 = -1e30f, rx1 = -1e30f;
#pragma unroll
        for (int nt = 0; nt < 8; nt++) {
            rx0 = fmaxf(rx0, fmaxf(s[nt][0], s[nt][1]));
            rx1 = fmaxf(rx1, fmaxf(s[nt][2], s[nt][3]));
        }
        rx0 = fmaxf(rx0, __shfl_xor_sync(0xffffffffu, rx0, 1));
        rx0 = fmaxf(rx0, __shfl_xor_sync(0xffffffffu, rx0, 2));
        rx1 = fmaxf(rx1, __shfl_xor_sync(0xffffffffu, rx1, 1));
        rx1 = fmaxf(rx1, __shfl_xor_sync(0xffffffffu, rx1, 2));

        float nm0 = fmaxf(m0, rx0), nm1 = fmaxf(m1, rx1);
        float c0 = exp2f(m0 - nm0), c1 = exp2f(m1 - nm1);
        m0 = nm0; m1 = nm1;

        float ps0 = 0.f, ps1 = 0.f;
#pragma unroll
        for (int nt = 0; nt < 8; nt++) {
            s[nt][0] = exp2f(s[nt][0] - nm0);
            s[nt][1] = exp2f(s[nt][1] - nm0);
            s[nt][2] = exp2f(s[nt][2] - nm1);
            s[nt][3] = exp2f(s[nt][3] - nm1);
            ps0 += s[nt][0] + s[nt][1];
            ps1 += s[nt][2] + s[nt][3];
        }
        ps0 += __shfl_xor_sync(0xffffffffu, ps0, 1);
        ps0 += __shfl_xor_sync(0xffffffffu, ps0, 2);
        ps1 += __shfl_xor_sync(0xffffffffu, ps1, 1);
        ps1 += __shfl_xor_sync(0xffffffffu, ps1, 2);
        l0 = l0 * c0 + ps0;
        l1 = l1 * c1 + ps1;

#pragma unroll
        for (int nt = 0; nt < 8; nt++) {
            o[nt][0] *= c0; o[nt][1] *= c0;
            o[nt][2] *= c1; o[nt][3] *= c1;
        }

        unsigned* pr0 = sP + (w * 16 + g) * SKS;
        unsigned* pr1 = pr0 + 8 * SKS;
#pragma unroll
        for (int nt = 0; nt < 8; nt++) {
            *(uint2*)(pr0 + 8 * nt + 2 * t) = make_uint2(f2tf32(s[nt][0]), f2tf32(s[nt][1]));
            *(uint2*)(pr1 + 8 * nt + 2 * t) = make_uint2(f2tf32(s[nt][2]), f2tf32(s[nt][3]));
        }
        __syncwarp();

#pragma unroll
        for (int kt = 0; kt < 8; kt++) {
            unsigned pa0 = pr0[8 * kt + t];
            unsigned pa1 = pr1[8 * kt + t];
            unsigned pa2 = pr0[8 * kt + t + 4];
            unsigned pa3 = pr1[8 * kt + t + 4];
#pragma unroll
            for (int nt = 0; nt < 8; nt++) {
                unsigned b0 = sV[(8 * kt + t) * SVS + 8 * nt + g];
                unsigned b1 = sV[(8 * kt + t + 4) * SVS + 8 * nt + g];
                mma_tf32(o[nt], pa0, pa1, pa2, pa3, b0, b1);
            }
        }
    }

    const float inv0 = 1.f / l0, inv1 = 1.f / l1;
    const int b = bh >> 4, h = bh & 15;
    const int r0 = q0 + w * 16 + g;
    float* op0 = out2 + ((size_t)b * SEQ + r0) * CDIM + h * HD;
    float* op1 = op0 + (size_t)8 * CDIM;
#pragma unroll
    for (int nt = 0; nt < 8; nt++) {
        *(float2*)(op0 + 8 * nt + 2 * t) = make_float2(o[nt][0] * inv0, o[nt][1] * inv0);
        *(float2*)(op1 + 8 * nt + 2 * t) = make_float2(o[nt][2] * inv1, o[nt][3] * inv1);
    }
}

// ---------------------------------------------------------------------------
// Kernel 3: proj GEMM (tf32 mma). out = (att2 + f) @ W + b
// ---------------------------------------------------------------------------
__global__ __launch_bounds__(128, 2) void proj_tc(const float* __restrict__ att2,
                                                  const float* __restrict__ F,
                                                  const float* __restrict__ W,
                                                  const float* __restrict__ bias,
                                                  float* __restrict__ out) {
    __shared__ unsigned sA[2][16][SAW];
    __shared__ unsigned sB[2][16][SAW];

    const int tid = threadIdx.x;
    const int lane = tid & 31;
    const int w = tid >> 5;
    const int g = lane >> 2, t = lane & 3;
    const int wm = w & 1, wn = w >> 1;

    const int m0 = blockIdx.y * 128;
    const int n0 = blockIdx.x * 128;

    float acc[4][8][4];
#pragma unroll
    for (int mt = 0; mt < 4; mt++)
#pragma unroll
        for (int nt = 0; nt < 8; nt++)
#pragma unroll
            for (int i = 0; i < 4; i++) acc[mt][nt][i] = 0.f;

    const int am = tid >> 2, at = tid & 3;
    const int bk = tid >> 5, bn = 4 * (tid & 31);

    const float* aptr = att2 + (size_t)(m0 + am) * CDIM + 4 * at;
    const float* fptr = F + (size_t)(m0 + am) * CDIM + 4 * at;
    const float* bptr = W + (size_t)bk * CDIM + n0 + bn;

    float4 ra[4], rb[4];
#pragma unroll
    for (int i = 0; i < 4; i++) {
        float4 x = *(const float4*)(aptr + (size_t)(32 * i) * CDIM);
        float4 y = *(const float4*)(fptr + (size_t)(32 * i) * CDIM);
        ra[i] = make_float4(x.x + y.x, x.y + y.y, x.z + y.z, x.w + y.w);
        rb[i] = *(const float4*)(bptr + (size_t)(4 * i) * CDIM);
    }

    int buf = 0;
#pragma unroll
    for (int i = 0; i < 4; i++) {
        unsigned* da = &sA[0][4 * at][am + 32 * i];
        da[0 * SAW] = f2tf32(ra[i].x);
        da[1 * SAW] = f2tf32(ra[i].y);
        da[2 * SAW] = f2tf32(ra[i].z);
        da[3 * SAW] = f2tf32(ra[i].w);
        uint4 pb = make_uint4(f2tf32(rb[i].x), f2tf32(rb[i].y),
                              f2tf32(rb[i].z), f2tf32(rb[i].w));
        *(uint4*)&sB[0][bk + 4 * i][bn] = pb;
    }
    __syncthreads();

    for (int k0 = 16; k0 <= CDIM; k0 += 16) {
        if (k0 < CDIM) {
#pragma unroll
            for (int i = 0; i < 4; i++) {
                float4 x = *(const float4*)(aptr + (size_t)(32 * i) * CDIM + k0);
                float4 y = *(const float4*)(fptr + (size_t)(32 * i) * CDIM + k0);
                ra[i] = make_float4(x.x + y.x, x.y + y.y, x.z + y.z, x.w + y.w);
                rb[i] = *(const float4*)(bptr + (size_t)(k0 + 4 * i) * CDIM);
            }
        }

#pragma unroll
        for (int kt = 0; kt < 2; kt++) {
            unsigned af[4][4];
#pragma unroll
            for (int mt = 0; mt < 4; mt++) {
                int mr = wm * 64 + mt * 16;
                af[mt][0] = sA[buf][kt * 8 + t][mr + g];
                af[mt][1] = sA[buf][kt * 8 + t][mr + g + 8];
                af[mt][2] = sA[buf][kt * 8 + t + 4][mr + g];
                af[mt][3] = sA[buf][kt * 8 + t + 4][mr + g + 8];
            }
#pragma unroll
            for (int nt = 0; nt < 8; nt++) {
                int nc = wn * 64 + nt * 8 + g;
                unsigned b0 = sB[buf][kt * 8 + t][nc];
                unsigned b1 = sB[buf][kt * 8 + t + 4][nc];
#pragma unroll
                for (int mt = 0; mt < 4; mt++)
                    mma_tf32(acc[mt][nt], af[mt][0], af[mt][1], af[mt][2], af[mt][3], b0, b1);
            }
        }

        if (k0 < CDIM) {
#pragma unroll
            for (int i = 0; i < 4; i++) {
                unsigned* da = &sA[buf ^ 1][4 * at][am + 32 * i];
                da[0 * SAW] = f2tf32(ra[i].x);
                da[1 * SAW] = f2tf32(ra[i].y);
                da[2 * SAW] = f2tf32(ra[i].z);
                da[3 * SAW] = f2tf32(ra[i].w);
                uint4 pb = make_uint4(f2tf32(rb[i].x), f2tf32(rb[i].y),
                                      f2tf32(rb[i].z), f2tf32(rb[i].w));
                *(uint4*)&sB[buf ^ 1][bk + 4 * i][bn] = pb;
            }
            __syncthreads();
            buf ^= 1;
        }
    }

#pragma unroll
    for (int mt = 0; mt < 4; mt++) {
#pragma unroll
        for (int nt = 0; nt < 8; nt++) {
            int col = n0 + wn * 64 + nt * 8 + 2 * t;
            float2 bb = *(const float2*)&bias[col];
            int row0 = m0 + wm * 64 + mt * 16 + g;
            float* p0 = out + (size_t)row0 * CDIM + col;
            float* p1 = out + (size_t)(row0 + 8) * CDIM + col;
            *(float2*)p0 = make_float2(acc[mt][nt][0] + bb.x, acc[mt][nt][1] + bb.y);
            *(float2*)p1 = make_float2(acc[mt][nt][2] + bb.x, acc[mt][nt][3] + bb.y);
        }
    }
}

extern "C" void kernel_launch(void* const* d_in, const int* in_sizes, int n_in,
                              void* d_out, int out_size) {
    const float* x     = (const float*)d_in[0];
    const float* f     = (const float*)d_in[1];
    const float* Wqkv  = (const float*)d_in[2];
    const float* Wproj = (const float*)d_in[3];
    const float* bproj = (const float*)d_in[4];
    float* out = (float*)d_out;

    const size_t half = (size_t)BATCH * SEQ * CDIM;
    float* att2;
    if ((size_t)out_size >= 2 * half) {
        att2 = out + half;
    } else {
        cudaGetSymbolAddress((void**)&att2, g_att_fallback);
    }

    cudaFuncSetAttribute(flash_attn_tc, cudaFuncAttributeMaxDynamicSharedMemorySize,
                         FLASH_SMEM);

    qkv_tc<<<dim3(QKVN / 128, ROWS / 128), 128>>>(x, Wqkv);
    flash_attn_tc<<<dim3(SEQ / 64, BHN), 128, FLASH_SMEM>>>(att2);
    proj_tc<<<dim3(CDIM / 128, ROWS / 128), 128>>>(att2, f, Wproj, bproj, out);
}